// round 8
// baseline (speedup 1.0000x reference)
#include <cuda_runtime.h>
#include <cuda_bf16.h>
#include <stdint.h>

// Problem dims (fixed by the dataset)
#define NBATCH 4
#define NROWS  8192
#define DMEM   128
#define NTILES 64
#define TILEB  32768        // 128 rows * 128 bf16 * 2B
#define THRESH 0.65f
#define HITCAP 65536

// Scratch (device globals are the sanctioned scratch mechanism)
__device__ __align__(16) __nv_bfloat16 g_proj[(size_t)NBATCH * NROWS * DMEM]; // 8 MB normalized proj
__device__ __align__(16) __nv_bfloat16 g_wb[DMEM * DMEM];                     // 32 KB bf16 W
__device__ float g_deg[NBATCH * NROWS];
__device__ uint2 g_hits[HITCAP];
__device__ unsigned g_hitcnt;

// ---------------------------------------------------------------------------
// helpers
// ---------------------------------------------------------------------------
__device__ __forceinline__ uint32_t su32(const void* p) {
    uint32_t a;
    asm("{ .reg .u64 t; cvta.to.shared.u64 t, %1; cvt.u32.u64 %0, t; }" : "=r"(a) : "l"(p));
    return a;
}

#define LDMATRIX_X4(r0, r1, r2, r3, addr) \
    asm volatile("ldmatrix.sync.aligned.m8n8.x4.shared.b16 {%0,%1,%2,%3}, [%4];" \
                 : "=r"(r0), "=r"(r1), "=r"(r2), "=r"(r3) : "r"(addr))

#define MMA_BF16(d, a, b0, b1) \
    asm volatile("mma.sync.aligned.m16n8k16.row.col.f32.bf16.bf16.f32 " \
                 "{%0,%1,%2,%3}, {%4,%5,%6,%7}, {%8,%9}, {%0,%1,%2,%3};" \
                 : "+f"((d)[0]), "+f"((d)[1]), "+f"((d)[2]), "+f"((d)[3]) \
                 : "r"((a)[0]), "r"((a)[1]), "r"((a)[2]), "r"((a)[3]), "r"(b0), "r"(b1))

// bf16 128x128 tile (32KB, 256B rows, 16 chunks/row, c^(r&7) swizzle). 256 thr.
__device__ __forceinline__ void copy_tile16(uint32_t dst, const __nv_bfloat16* src, int tid) {
    #pragma unroll
    for (int k = 0; k < 8; k++) {
        int idx = tid + k * 256;
        int r = idx >> 4, c = idx & 15;
        uint32_t doff = (uint32_t)(r * 256 + ((c ^ (r & 7)) << 4));
        asm volatile("cp.async.cg.shared.global [%0], [%1], 16;"
                     :: "r"(dst + doff), "l"((const char*)src + (size_t)idx * 16) : "memory");
    }
}

// Load this warp's resident A fragments (m32 x k128) from swizzled smA.
__device__ __forceinline__ void load_afrags(uint32_t a[2][8][4], uint32_t smA, int wm, int l) {
    #pragma unroll
    for (int m = 0; m < 2; m++)
        #pragma unroll
        for (int k = 0; k < 8; k++) {
            int r = wm * 32 + m * 16 + (l & 15);
            int chunk = k * 2 + ((l >> 4) & 1);
            uint32_t addr = smA + r * 256 + ((chunk ^ (r & 7)) << 4);
            LDMATRIX_X4(a[m][k][0], a[m][k][1], a[m][k][2], a[m][k][3], addr);
        }
}

// ---------------------------------------------------------------------------
// Stage 0 (tiny): W -> bf16; zero g_deg; reset hit counter
// ---------------------------------------------------------------------------
__global__ void __launch_bounds__(256) prep_kernel(const float* __restrict__ W) {
    int b = blockIdx.x, tid = threadIdx.x;
    if (b == 0 && tid == 0) g_hitcnt = 0u;
    if (b < 8) {                                       // W -> bf16
        size_t g = ((size_t)b * 256 + tid) * 2;
        float4 a0 = reinterpret_cast<const float4*>(W)[g];
        float4 a1 = reinterpret_cast<const float4*>(W)[g + 1];
        __nv_bfloat162 h0 = __floats2bfloat162_rn(a0.x, a0.y);
        __nv_bfloat162 h1 = __floats2bfloat162_rn(a0.z, a0.w);
        __nv_bfloat162 h2 = __floats2bfloat162_rn(a1.x, a1.y);
        __nv_bfloat162 h3 = __floats2bfloat162_rn(a1.z, a1.w);
        reinterpret_cast<uint4*>(g_wb)[g / 2] =
            make_uint4(*(uint32_t*)&h0, *(uint32_t*)&h1, *(uint32_t*)&h2, *(uint32_t*)&h3);
    } else {                                           // zero g_deg (32768 floats)
        size_t g = ((size_t)(b - 8) * 256 + tid) * 2;
        reinterpret_cast<float4*>(g_deg)[g]     = make_float4(0.f, 0.f, 0.f, 0.f);
        reinterpret_cast<float4*>(g_deg)[g + 1] = make_float4(0.f, 0.f, 0.f, 0.f);
    }
}

// ---------------------------------------------------------------------------
// Stage 1: proj = normalize(X @ W^T + b) -> bf16 row-major, via bf16 mma.
// Also writes out = X (analytic adjacency-diagonal term) while X is in flight.
// CTA: 256 thr, 8 warps; warp w owns rows w*16..+15, full n=128.
// ---------------------------------------------------------------------------
__global__ void __launch_bounds__(256) proj_kernel(const float* __restrict__ X,
                                                   const float* __restrict__ Bv,
                                                   float* __restrict__ out) {
    extern __shared__ unsigned char dsm[];
    uint32_t smX = su32(dsm);            // 32 KB (swizzled)
    uint32_t smW = smX + TILEB;          // 32 KB (swizzled)
    float* bs = (float*)(dsm + 2 * TILEB);

    int tid = threadIdx.x, w = tid >> 5, l = tid & 31;
    int r0 = blockIdx.x * 128;

    copy_tile16(smW, g_wb, tid);
    asm volatile("cp.async.commit_group;" ::: "memory");
    if (tid < 128) bs[tid] = Bv[tid];

    // X fp32 -> bf16 into swizzled smem; forward fp32 to out (out = X).
    #pragma unroll
    for (int k = 0; k < 8; k++) {
        int idx = tid + k * 256;
        int r = idx >> 4, c = idx & 15;
        size_t gbase = ((size_t)(r0 + r) * DMEM + c * 8);
        float4 f0 = reinterpret_cast<const float4*>(X + gbase)[0];
        float4 f1 = reinterpret_cast<const float4*>(X + gbase)[1];
        reinterpret_cast<float4*>(out + gbase)[0] = f0;
        reinterpret_cast<float4*>(out + gbase)[1] = f1;
        __nv_bfloat162 h0 = __floats2bfloat162_rn(f0.x, f0.y);
        __nv_bfloat162 h1 = __floats2bfloat162_rn(f0.z, f0.w);
        __nv_bfloat162 h2 = __floats2bfloat162_rn(f1.x, f1.y);
        __nv_bfloat162 h3 = __floats2bfloat162_rn(f1.z, f1.w);
        *reinterpret_cast<uint4*>(dsm + r * 256 + ((c ^ (r & 7)) << 4)) =
            make_uint4(*(uint32_t*)&h0, *(uint32_t*)&h1, *(uint32_t*)&h2, *(uint32_t*)&h3);
    }
    asm volatile("cp.async.wait_group 0;" ::: "memory");
    __syncthreads();

    float acc[16][4];
    #pragma unroll
    for (int f = 0; f < 16; f++)
        #pragma unroll
        for (int p = 0; p < 4; p++) acc[f][p] = 0.f;

    #pragma unroll
    for (int k = 0; k < 8; k++) {
        uint32_t a[4];
        {
            int r = w * 16 + (l & 15);
            int chunk = k * 2 + ((l >> 4) & 1);
            uint32_t addr = smX + r * 256 + ((chunk ^ (r & 7)) << 4);
            LDMATRIX_X4(a[0], a[1], a[2], a[3], addr);
        }
        #pragma unroll
        for (int nf = 0; nf < 8; nf++) {
            int nn = nf * 16 + (l & 7) + ((l & 16) ? 8 : 0);
            int chunk = k * 2 + ((l >> 3) & 1);
            uint32_t addr = smW + nn * 256 + ((chunk ^ (nn & 7)) << 4);
            uint32_t b0, b1, b2, b3;
            LDMATRIX_X4(b0, b1, b2, b3, addr);
            MMA_BF16(acc[nf * 2],     a, b0, b1);
            MMA_BF16(acc[nf * 2 + 1], a, b2, b3);
        }
    }

    // bias + row sums of squares (rows l/4 and l/4+8 of this warp's m16)
    float slo = 0.f, shi = 0.f;
    #pragma unroll
    for (int f = 0; f < 16; f++) {
        int c0 = f * 8 + 2 * (l & 3);
        float b0 = bs[c0], b1 = bs[c0 + 1];
        acc[f][0] += b0; acc[f][1] += b1;
        acc[f][2] += b0; acc[f][3] += b1;
        slo += acc[f][0] * acc[f][0] + acc[f][1] * acc[f][1];
        shi += acc[f][2] * acc[f][2] + acc[f][3] * acc[f][3];
    }
    slo += __shfl_xor_sync(0xffffffffu, slo, 1);
    slo += __shfl_xor_sync(0xffffffffu, slo, 2);
    shi += __shfl_xor_sync(0xffffffffu, shi, 1);
    shi += __shfl_xor_sync(0xffffffffu, shi, 2);
    float rlo = rsqrtf(fmaxf(slo, 1e-24f));
    float rhi = rsqrtf(fmaxf(shi, 1e-24f));

    int rowlo = r0 + w * 16 + (l >> 2);
    #pragma unroll
    for (int f = 0; f < 16; f++) {
        int c0 = f * 8 + 2 * (l & 3);
        __nv_bfloat162 hlo = __floats2bfloat162_rn(acc[f][0] * rlo, acc[f][1] * rlo);
        __nv_bfloat162 hhi = __floats2bfloat162_rn(acc[f][2] * rhi, acc[f][3] * rhi);
        *reinterpret_cast<uint32_t*>(g_proj + (size_t)rowlo * DMEM + c0)       = *(uint32_t*)&hlo;
        *reinterpret_cast<uint32_t*>(g_proj + (size_t)(rowlo + 8) * DMEM + c0) = *(uint32_t*)&hhi;
    }
}

// ---------------------------------------------------------------------------
// Stage 2: upper-triangular sim tiles (jt >= it) via bf16 mma. R7 structure;
// the rare-hit path now only APPENDS (i,j) pairs to a global list (compact
// cold code, no X loads / out atomics in this kernel).
// ---------------------------------------------------------------------------
__global__ void __launch_bounds__(256, 2) sim_kernel(const float* __restrict__ X,
                                                     float* __restrict__ out) {
    extern __shared__ unsigned char dsm[];
    uint32_t smA  = su32(dsm);
    uint32_t smB0 = smA + TILEB;
    uint32_t smB1 = smA + 2 * TILEB;

    int tid = threadIdx.x, wid = tid >> 5, l = tid & 31;
    int wm = wid >> 1, wn = wid & 1;

    int bid = blockIdx.x;
    int batch = bid >> 7;
    int p     = (bid >> 2) & 31;
    int q     = bid & 3;
    int n0    = NTILES - p;                 // tiles in row p
    int t0 = (q * 65) >> 2, t1 = ((q + 1) * 65) >> 2;

    const __nv_bfloat16* pb = g_proj + (size_t)batch * NROWS * DMEM;
    int bi = batch * NROWS;                 // global row offset for this batch

    #define JOF(t) (((t) < n0) ? (p + (t)) : ((63 - p) + ((t) - n0)))
    #define IOF(t) (((t) < n0) ? p : (63 - p))

    int cur_i = IOF(t0);
    copy_tile16(smA, pb + (size_t)cur_i * 128 * DMEM, tid);
    copy_tile16(smB0, pb + (size_t)JOF(t0) * 128 * DMEM, tid);
    asm volatile("cp.async.commit_group;" ::: "memory");
    if (t0 + 1 < t1)
        copy_tile16(smB1, pb + (size_t)JOF(t0 + 1) * 128 * DMEM, tid);
    asm volatile("cp.async.commit_group;" ::: "memory");
    asm volatile("cp.async.wait_group 1;" ::: "memory");
    __syncthreads();

    uint32_t a[2][8][4];
    load_afrags(a, smA, wm, l);

    for (int t = t0; t < t1; t++) {
        if (IOF(t) != cur_i) {             // row crossing: reload A (once per CTA)
            cur_i = IOF(t);
            __syncthreads();
            copy_tile16(smA, pb + (size_t)cur_i * 128 * DMEM, tid);
            asm volatile("cp.async.commit_group;" ::: "memory");
            asm volatile("cp.async.wait_group 0;" ::: "memory");
            __syncthreads();
            load_afrags(a, smA, wm, l);
        }
        int it = cur_i, jt = JOF(t);
        uint32_t smB = ((t - t0) & 1) ? smB1 : smB0;

        #pragma unroll 1
        for (int g = 0; g < 4; g++) {
            int n0c = wn * 64 + g * 16;
            float d[2][2][4];
            #pragma unroll
            for (int m = 0; m < 2; m++)
                #pragma unroll
                for (int h = 0; h < 2; h++)
                    #pragma unroll
                    for (int pp = 0; pp < 4; pp++) d[m][h][pp] = 0.f;

            #pragma unroll
            for (int k = 0; k < 8; k++) {
                int nn = n0c + (l & 7) + ((l & 16) ? 8 : 0);
                int chunk = k * 2 + ((l >> 3) & 1);
                uint32_t addr = smB + nn * 256 + ((chunk ^ (nn & 7)) << 4);
                uint32_t b0, b1, b2, b3;
                LDMATRIX_X4(b0, b1, b2, b3, addr);
                #pragma unroll
                for (int m = 0; m < 2; m++) {
                    MMA_BF16(d[m][0], a[m][k], b0, b1);
                    MMA_BF16(d[m][1], a[m][k], b2, b3);
                }
            }

            float vmax = d[0][0][0];
            #pragma unroll
            for (int m = 0; m < 2; m++)
                #pragma unroll
                for (int h = 0; h < 2; h++)
                    #pragma unroll
                    for (int pp = 0; pp < 4; pp++) vmax = fmaxf(vmax, d[m][h][pp]);
            unsigned warp_any = __ballot_sync(0xffffffffu, vmax > THRESH);

            if (warp_any) {   // rare: diagonal tile self-sim, or a true hit.
                bool diag = (it == jt);
                #pragma unroll
                for (int m = 0; m < 2; m++)
                    #pragma unroll
                    for (int h = 0; h < 2; h++)
                        #pragma unroll
                        for (int pp = 0; pp < 4; pp++) {
                            if (d[m][h][pp] > THRESH) {
                                int ib = bi + it * 128 + wm * 32 + m * 16 + (l >> 2) + ((pp & 2) ? 8 : 0);
                                int jb = bi + jt * 128 + n0c + h * 8 + 2 * (l & 3) + (pp & 1);
                                if (ib != jb) {
                                    unsigned idx = atomicAdd(&g_hitcnt, diag ? 1u : 2u);
                                    if (idx < HITCAP)
                                        g_hits[idx] = make_uint2((unsigned)ib, (unsigned)jb);
                                    if (!diag && idx + 1 < HITCAP)
                                        g_hits[idx + 1] = make_uint2((unsigned)jb, (unsigned)ib);
                                }
                            }
                        }
            }
        }

        __syncthreads();
        if (t + 2 < t1)
            copy_tile16(smB, pb + (size_t)JOF(t + 2) * 128 * DMEM, tid);
        asm volatile("cp.async.commit_group;" ::: "memory");
        asm volatile("cp.async.wait_group 1;" ::: "memory");
        __syncthreads();
    }
    #undef JOF
    #undef IOF
}

// ---------------------------------------------------------------------------
// Stage 2b: replay the (tiny) hit list: out[i] += X[j], deg[i] += 1.
// One warp per hit, grid-stride. Atomics: a row may receive several hits.
// ---------------------------------------------------------------------------
__global__ void __launch_bounds__(128) hits_kernel(const float* __restrict__ X,
                                                   float* __restrict__ out) {
    unsigned nh = g_hitcnt;
    if (nh > HITCAP) nh = HITCAP;
    int w = blockIdx.x * 4 + (threadIdx.x >> 5);
    int l = threadIdx.x & 31;
    for (unsigned h = w; h < nh; h += gridDim.x * 4) {
        uint2 pr = g_hits[h];
        float4 xv = reinterpret_cast<const float4*>(X + (size_t)pr.y * DMEM)[l];
        float* o = out + (size_t)pr.x * DMEM + l * 4;
        atomicAdd(o + 0, xv.x); atomicAdd(o + 1, xv.y);
        atomicAdd(o + 2, xv.z); atomicAdd(o + 3, xv.w);
        if (l == 0) atomicAdd(&g_deg[pr.x], 1.0f);
    }
}

// ---------------------------------------------------------------------------
// Stage 3: rows with hits only: out[i] *= 1/(1 + deg[i]). deg==0 rows untouched.
// ---------------------------------------------------------------------------
__global__ void __launch_bounds__(256) fin_kernel(float* __restrict__ out) {
    int row = blockIdx.x * 256 + threadIdx.x;
    float dg = g_deg[row];
    if (dg != 0.0f) {
        float inv = 1.0f / (1.0f + dg);
        float4* o = reinterpret_cast<float4*>(out + (size_t)row * DMEM);
        #pragma unroll
        for (int t = 0; t < DMEM / 4; t++) {
            float4 v = o[t];
            v.x *= inv; v.y *= inv; v.z *= inv; v.w *= inv;
            o[t] = v;
        }
    }
}

// ---------------------------------------------------------------------------
extern "C" void kernel_launch(void* const* d_in, const int* in_sizes, int n_in,
                              void* d_out, int out_size) {
    (void)in_sizes; (void)n_in; (void)out_size;
    const float* X  = (const float*)d_in[0];
    const float* W  = (const float*)d_in[1];
    const float* Bv = (const float*)d_in[2];
    float* out = (float*)d_out;

    const int PROJ_SMEM = 2 * TILEB + 512;     // ~66 KB
    const int SIM_SMEM  = 3 * TILEB;           // 96 KB (2 CTAs/SM)
    cudaFuncSetAttribute(proj_kernel, cudaFuncAttributeMaxDynamicSharedMemorySize, PROJ_SMEM);
    cudaFuncSetAttribute(sim_kernel,  cudaFuncAttributeMaxDynamicSharedMemorySize, SIM_SMEM);

    prep_kernel<<<24, 256>>>(W);
    proj_kernel<<<(NBATCH * NROWS) / 128, 256, PROJ_SMEM>>>(X, Bv, out);
    sim_kernel<<<NBATCH * 32 * 4, 256, SIM_SMEM>>>(X, out);
    hits_kernel<<<32, 128>>>(X, out);
    fin_kernel<<<NBATCH * NROWS / 256, 256>>>(out);
}

// round 9
// speedup vs baseline: 1.1132x; 1.1132x over previous
#include <cuda_runtime.h>
#include <cuda_bf16.h>
#include <stdint.h>

// Problem dims (fixed by the dataset)
#define NBATCH 4
#define NROWS  8192
#define DMEM   128
#define NTILES 64
#define TILEB  32768        // 128 rows * 128 bf16 * 2B
#define THRESH 0.65f
#define HITCAP 65536

// Scratch (device globals are the sanctioned scratch mechanism)
__device__ __align__(16) __nv_bfloat16 g_proj[(size_t)NBATCH * NROWS * DMEM]; // 8 MB normalized proj
__device__ __align__(16) __nv_bfloat16 g_wb[DMEM * DMEM];                     // 32 KB bf16 W
__device__ uint2 g_hits[HITCAP];
__device__ unsigned g_hitcnt;

// ---------------------------------------------------------------------------
// helpers
// ---------------------------------------------------------------------------
__device__ __forceinline__ uint32_t su32(const void* p) {
    uint32_t a;
    asm("{ .reg .u64 t; cvta.to.shared.u64 t, %1; cvt.u32.u64 %0, t; }" : "=r"(a) : "l"(p));
    return a;
}

#define LDMATRIX_X4(r0, r1, r2, r3, addr) \
    asm volatile("ldmatrix.sync.aligned.m8n8.x4.shared.b16 {%0,%1,%2,%3}, [%4];" \
                 : "=r"(r0), "=r"(r1), "=r"(r2), "=r"(r3) : "r"(addr))

#define MMA_BF16(d, a, b0, b1) \
    asm volatile("mma.sync.aligned.m16n8k16.row.col.f32.bf16.bf16.f32 " \
                 "{%0,%1,%2,%3}, {%4,%5,%6,%7}, {%8,%9}, {%0,%1,%2,%3};" \
                 : "+f"((d)[0]), "+f"((d)[1]), "+f"((d)[2]), "+f"((d)[3]) \
                 : "r"((a)[0]), "r"((a)[1]), "r"((a)[2]), "r"((a)[3]), "r"(b0), "r"(b1))

// bf16 128x128 tile (32KB, 256B rows, 16 chunks/row, c^(r&7) swizzle). 256 thr.
__device__ __forceinline__ void copy_tile16(uint32_t dst, const __nv_bfloat16* src, int tid) {
    #pragma unroll
    for (int k = 0; k < 8; k++) {
        int idx = tid + k * 256;
        int r = idx >> 4, c = idx & 15;
        uint32_t doff = (uint32_t)(r * 256 + ((c ^ (r & 7)) << 4));
        asm volatile("cp.async.cg.shared.global [%0], [%1], 16;"
                     :: "r"(dst + doff), "l"((const char*)src + (size_t)idx * 16) : "memory");
    }
}

// Load this warp's resident A fragments (m32 x k128) from swizzled smA.
__device__ __forceinline__ void load_afrags(uint32_t a[2][8][4], uint32_t smA, int wm, int l) {
    #pragma unroll
    for (int m = 0; m < 2; m++)
        #pragma unroll
        for (int k = 0; k < 8; k++) {
            int r = wm * 32 + m * 16 + (l & 15);
            int chunk = k * 2 + ((l >> 4) & 1);
            uint32_t addr = smA + r * 256 + ((chunk ^ (r & 7)) << 4);
            LDMATRIX_X4(a[m][k][0], a[m][k][1], a[m][k][2], a[m][k][3], addr);
        }
}

// ---------------------------------------------------------------------------
// Stage 0 (tiny): W -> bf16; reset hit counter
// ---------------------------------------------------------------------------
__global__ void __launch_bounds__(256) prep_kernel(const float* __restrict__ W) {
    int b = blockIdx.x, tid = threadIdx.x;
    if (b == 0 && tid == 0) g_hitcnt = 0u;
    size_t g = ((size_t)b * 256 + tid) * 2;
    float4 a0 = reinterpret_cast<const float4*>(W)[g];
    float4 a1 = reinterpret_cast<const float4*>(W)[g + 1];
    __nv_bfloat162 h0 = __floats2bfloat162_rn(a0.x, a0.y);
    __nv_bfloat162 h1 = __floats2bfloat162_rn(a0.z, a0.w);
    __nv_bfloat162 h2 = __floats2bfloat162_rn(a1.x, a1.y);
    __nv_bfloat162 h3 = __floats2bfloat162_rn(a1.z, a1.w);
    reinterpret_cast<uint4*>(g_wb)[g / 2] =
        make_uint4(*(uint32_t*)&h0, *(uint32_t*)&h1, *(uint32_t*)&h2, *(uint32_t*)&h3);
}

// ---------------------------------------------------------------------------
// Stage 1: proj = normalize(X @ W^T + b) -> bf16 row-major, via bf16 mma.
// Also writes out = X (analytic adjacency-diagonal term) while X is in flight.
// CTA: 256 thr, 8 warps; warp w owns rows w*16..+15, full n=128.
// ---------------------------------------------------------------------------
__global__ void __launch_bounds__(256) proj_kernel(const float* __restrict__ X,
                                                   const float* __restrict__ Bv,
                                                   float* __restrict__ out) {
    extern __shared__ unsigned char dsm[];
    uint32_t smX = su32(dsm);            // 32 KB (swizzled)
    uint32_t smW = smX + TILEB;          // 32 KB (swizzled)
    float* bs = (float*)(dsm + 2 * TILEB);

    int tid = threadIdx.x, w = tid >> 5, l = tid & 31;
    int r0 = blockIdx.x * 128;

    copy_tile16(smW, g_wb, tid);
    asm volatile("cp.async.commit_group;" ::: "memory");
    if (tid < 128) bs[tid] = Bv[tid];

    // X fp32 -> bf16 into swizzled smem; forward fp32 to out (out = X).
    #pragma unroll
    for (int k = 0; k < 8; k++) {
        int idx = tid + k * 256;
        int r = idx >> 4, c = idx & 15;
        size_t gbase = ((size_t)(r0 + r) * DMEM + c * 8);
        float4 f0 = reinterpret_cast<const float4*>(X + gbase)[0];
        float4 f1 = reinterpret_cast<const float4*>(X + gbase)[1];
        reinterpret_cast<float4*>(out + gbase)[0] = f0;
        reinterpret_cast<float4*>(out + gbase)[1] = f1;
        __nv_bfloat162 h0 = __floats2bfloat162_rn(f0.x, f0.y);
        __nv_bfloat162 h1 = __floats2bfloat162_rn(f0.z, f0.w);
        __nv_bfloat162 h2 = __floats2bfloat162_rn(f1.x, f1.y);
        __nv_bfloat162 h3 = __floats2bfloat162_rn(f1.z, f1.w);
        *reinterpret_cast<uint4*>(dsm + r * 256 + ((c ^ (r & 7)) << 4)) =
            make_uint4(*(uint32_t*)&h0, *(uint32_t*)&h1, *(uint32_t*)&h2, *(uint32_t*)&h3);
    }
    asm volatile("cp.async.wait_group 0;" ::: "memory");
    __syncthreads();

    float acc[16][4];
    #pragma unroll
    for (int f = 0; f < 16; f++)
        #pragma unroll
        for (int p = 0; p < 4; p++) acc[f][p] = 0.f;

    #pragma unroll
    for (int k = 0; k < 8; k++) {
        uint32_t a[4];
        {
            int r = w * 16 + (l & 15);
            int chunk = k * 2 + ((l >> 4) & 1);
            uint32_t addr = smX + r * 256 + ((chunk ^ (r & 7)) << 4);
            LDMATRIX_X4(a[0], a[1], a[2], a[3], addr);
        }
        #pragma unroll
        for (int nf = 0; nf < 8; nf++) {
            int nn = nf * 16 + (l & 7) + ((l & 16) ? 8 : 0);
            int chunk = k * 2 + ((l >> 3) & 1);
            uint32_t addr = smW + nn * 256 + ((chunk ^ (nn & 7)) << 4);
            uint32_t b0, b1, b2, b3;
            LDMATRIX_X4(b0, b1, b2, b3, addr);
            MMA_BF16(acc[nf * 2],     a, b0, b1);
            MMA_BF16(acc[nf * 2 + 1], a, b2, b3);
        }
    }

    // bias + row sums of squares (rows l/4 and l/4+8 of this warp's m16)
    float slo = 0.f, shi = 0.f;
    #pragma unroll
    for (int f = 0; f < 16; f++) {
        int c0 = f * 8 + 2 * (l & 3);
        float b0 = bs[c0], b1 = bs[c0 + 1];
        acc[f][0] += b0; acc[f][1] += b1;
        acc[f][2] += b0; acc[f][3] += b1;
        slo += acc[f][0] * acc[f][0] + acc[f][1] * acc[f][1];
        shi += acc[f][2] * acc[f][2] + acc[f][3] * acc[f][3];
    }
    slo += __shfl_xor_sync(0xffffffffu, slo, 1);
    slo += __shfl_xor_sync(0xffffffffu, slo, 2);
    shi += __shfl_xor_sync(0xffffffffu, shi, 1);
    shi += __shfl_xor_sync(0xffffffffu, shi, 2);
    float rlo = rsqrtf(fmaxf(slo, 1e-24f));
    float rhi = rsqrtf(fmaxf(shi, 1e-24f));

    int rowlo = r0 + w * 16 + (l >> 2);
    #pragma unroll
    for (int f = 0; f < 16; f++) {
        int c0 = f * 8 + 2 * (l & 3);
        __nv_bfloat162 hlo = __floats2bfloat162_rn(acc[f][0] * rlo, acc[f][1] * rlo);
        __nv_bfloat162 hhi = __floats2bfloat162_rn(acc[f][2] * rhi, acc[f][3] * rhi);
        *reinterpret_cast<uint32_t*>(g_proj + (size_t)rowlo * DMEM + c0)       = *(uint32_t*)&hlo;
        *reinterpret_cast<uint32_t*>(g_proj + (size_t)(rowlo + 8) * DMEM + c0) = *(uint32_t*)&hhi;
    }
}

// ---------------------------------------------------------------------------
// Stage 2: upper-triangular sim tiles (jt >= it) via bf16 mma.
// CTA = (batch, pair p, eighth q): 1024 CTAs x 8-9 tiles (fine granularity).
// Rare hits append (i,j) [+ symmetric partner] to a global list.
// ---------------------------------------------------------------------------
__global__ void __launch_bounds__(256, 2) sim_kernel() {
    extern __shared__ unsigned char dsm[];
    uint32_t smA  = su32(dsm);
    uint32_t smB0 = smA + TILEB;
    uint32_t smB1 = smA + 2 * TILEB;

    int tid = threadIdx.x, wid = tid >> 5, l = tid & 31;
    int wm = wid >> 1, wn = wid & 1;

    int bid = blockIdx.x;
    int batch = bid >> 8;
    int p     = (bid >> 3) & 31;
    int q     = bid & 7;
    int n0    = NTILES - p;                 // tiles in row p
    int t0 = (q * 65) >> 3, t1 = ((q + 1) * 65) >> 3;

    const __nv_bfloat16* pb = g_proj + (size_t)batch * NROWS * DMEM;
    int bi = batch * NROWS;                 // global row offset for this batch

    #define JOF(t) (((t) < n0) ? (p + (t)) : ((63 - p) + ((t) - n0)))
    #define IOF(t) (((t) < n0) ? p : (63 - p))

    int cur_i = IOF(t0);
    copy_tile16(smA, pb + (size_t)cur_i * 128 * DMEM, tid);
    copy_tile16(smB0, pb + (size_t)JOF(t0) * 128 * DMEM, tid);
    asm volatile("cp.async.commit_group;" ::: "memory");
    if (t0 + 1 < t1)
        copy_tile16(smB1, pb + (size_t)JOF(t0 + 1) * 128 * DMEM, tid);
    asm volatile("cp.async.commit_group;" ::: "memory");
    asm volatile("cp.async.wait_group 1;" ::: "memory");
    __syncthreads();

    uint32_t a[2][8][4];
    load_afrags(a, smA, wm, l);

    for (int t = t0; t < t1; t++) {
        if (IOF(t) != cur_i) {             // row crossing (only 1-in-8 CTAs)
            cur_i = IOF(t);
            __syncthreads();
            copy_tile16(smA, pb + (size_t)cur_i * 128 * DMEM, tid);
            asm volatile("cp.async.commit_group;" ::: "memory");
            asm volatile("cp.async.wait_group 0;" ::: "memory");
            __syncthreads();
            load_afrags(a, smA, wm, l);
        }
        int it = cur_i, jt = JOF(t);
        uint32_t smB = ((t - t0) & 1) ? smB1 : smB0;

        #pragma unroll 1
        for (int g = 0; g < 4; g++) {
            int n0c = wn * 64 + g * 16;
            float d[2][2][4];
            #pragma unroll
            for (int m = 0; m < 2; m++)
                #pragma unroll
                for (int h = 0; h < 2; h++)
                    #pragma unroll
                    for (int pp = 0; pp < 4; pp++) d[m][h][pp] = 0.f;

            #pragma unroll
            for (int k = 0; k < 8; k++) {
                int nn = n0c + (l & 7) + ((l & 16) ? 8 : 0);
                int chunk = k * 2 + ((l >> 3) & 1);
                uint32_t addr = smB + nn * 256 + ((chunk ^ (nn & 7)) << 4);
                uint32_t b0, b1, b2, b3;
                LDMATRIX_X4(b0, b1, b2, b3, addr);
                #pragma unroll
                for (int m = 0; m < 2; m++) {
                    MMA_BF16(d[m][0], a[m][k], b0, b1);
                    MMA_BF16(d[m][1], a[m][k], b2, b3);
                }
            }

            float vmax = d[0][0][0];
            #pragma unroll
            for (int m = 0; m < 2; m++)
                #pragma unroll
                for (int h = 0; h < 2; h++)
                    #pragma unroll
                    for (int pp = 0; pp < 4; pp++) vmax = fmaxf(vmax, d[m][h][pp]);
            unsigned warp_any = __ballot_sync(0xffffffffu, vmax > THRESH);

            if (warp_any) {   // rare: diagonal tile self-sim, or a true hit
                bool diag = (it == jt);
                #pragma unroll
                for (int m = 0; m < 2; m++)
                    #pragma unroll
                    for (int h = 0; h < 2; h++)
                        #pragma unroll
                        for (int pp = 0; pp < 4; pp++) {
                            if (d[m][h][pp] > THRESH) {
                                int ib = bi + it * 128 + wm * 32 + m * 16 + (l >> 2) + ((pp & 2) ? 8 : 0);
                                int jb = bi + jt * 128 + n0c + h * 8 + 2 * (l & 3) + (pp & 1);
                                if (ib != jb) {
                                    unsigned idx = atomicAdd(&g_hitcnt, diag ? 1u : 2u);
                                    if (idx < HITCAP)
                                        g_hits[idx] = make_uint2((unsigned)ib, (unsigned)jb);
                                    if (!diag && idx + 1 < HITCAP)
                                        g_hits[idx + 1] = make_uint2((unsigned)jb, (unsigned)ib);
                                }
                            }
                        }
            }
        }

        __syncthreads();
        if (t + 2 < t1)
            copy_tile16(smB, pb + (size_t)JOF(t + 2) * 128 * DMEM, tid);
        asm volatile("cp.async.commit_group;" ::: "memory");
        asm volatile("cp.async.wait_group 1;" ::: "memory");
        __syncthreads();
    }
    #undef JOF
    #undef IOF
}

// ---------------------------------------------------------------------------
// Stage 3 (merged hits+fin): per row, scan the (tiny) hit list; if this row
// has hits: out[row] = (X[row] + sum_j X[j]) / (1 + deg). Else untouched.
// ---------------------------------------------------------------------------
__global__ void __launch_bounds__(256) fin_kernel(const float* __restrict__ X,
                                                  float* __restrict__ out) {
    unsigned row = blockIdx.x * 256 + threadIdx.x;
    unsigned nh = g_hitcnt;
    if (nh > HITCAP) nh = HITCAP;
    int deg = 0;
    for (unsigned h = 0; h < nh; h++)
        if (g_hits[h].x == row) deg++;
    if (deg > 0) {
        float inv = 1.0f / (1.0f + (float)deg);
        float* o = out + (size_t)row * DMEM;
        #pragma unroll 4
        for (int dcol = 0; dcol < DMEM; dcol++) {
            float acc = o[dcol];                      // == X[row][dcol]
            for (unsigned h = 0; h < nh; h++)
                if (g_hits[h].x == row)
                    acc += X[(size_t)g_hits[h].y * DMEM + dcol];
            o[dcol] = acc * inv;
        }
    }
}

// ---------------------------------------------------------------------------
extern "C" void kernel_launch(void* const* d_in, const int* in_sizes, int n_in,
                              void* d_out, int out_size) {
    (void)in_sizes; (void)n_in; (void)out_size;
    const float* X  = (const float*)d_in[0];
    const float* W  = (const float*)d_in[1];
    const float* Bv = (const float*)d_in[2];
    float* out = (float*)d_out;

    const int PROJ_SMEM = 2 * TILEB + 512;     // ~66 KB
    const int SIM_SMEM  = 3 * TILEB;           // 96 KB (2 CTAs/SM)
    cudaFuncSetAttribute(proj_kernel, cudaFuncAttributeMaxDynamicSharedMemorySize, PROJ_SMEM);
    cudaFuncSetAttribute(sim_kernel,  cudaFuncAttributeMaxDynamicSharedMemorySize, SIM_SMEM);

    prep_kernel<<<8, 256>>>(W);
    proj_kernel<<<(NBATCH * NROWS) / 128, 256, PROJ_SMEM>>>(X, Bv, out);
    sim_kernel<<<NBATCH * 32 * 8, 256, SIM_SMEM>>>();
    fin_kernel<<<NBATCH * NROWS / 256, 256>>>(X, out);
}